// round 8
// baseline (speedup 1.0000x reference)
#include <cuda_runtime.h>
#include <cuda_bf16.h>
#include <cstdint>

#define NMAX 50000
#define EMAX 800000
#define DD   128
#define GMAX 512

// Scratch (no allocation allowed; __device__ globals are the sanctioned path).
__device__ __align__(16) float g_dinv[NMAX];
__device__ __align__(16) float g_bufA[(size_t)NMAX * DD];
__device__ __align__(16) float g_bufB[(size_t)NMAX * DD];
__device__ __align__(16) float g_bufC[(size_t)NMAX * DD];
__device__ __align__(16) float g_cnt[GMAX];
// CSR scratch
__device__ __align__(16) int g_rowcnt[NMAX];
__device__ __align__(16) int g_fillcnt[NMAX];
__device__ __align__(16) int g_rowstart[NMAX + 1];
__device__ __align__(16) int g_col[EMAX];
// 1 if integer inputs are int64, 0 if int32 (JAX x64-disabled datasets)
__device__ int g_is64;

// ---------------------------------------------------------------------------
// Dtype detection: if edge_index is int64 (values < 2^31, nonneg), every odd
// int32 word is 0. Sample the first 2048 elements (16KB — in bounds whether
// the buffer is 6.4MB int32 or 12.8MB int64).
// ---------------------------------------------------------------------------
__global__ void k_detect(const int* __restrict__ p, int nSample, int* flag64) {
    __shared__ int s_any;
    if (threadIdx.x == 0) s_any = 0;
    __syncthreads();
    int acc = 0;
    for (int k = threadIdx.x; k < nSample; k += blockDim.x) acc |= p[2 * k + 1];
    if (acc) atomicOr(&s_any, 1);
    __syncthreads();
    if (threadIdx.x == 0) *flag64 = (s_any == 0) ? 1 : 0;
}

__device__ __forceinline__ int idx_at(const void* p, size_t i, int f64) {
    return f64 ? (int)((const long long*)p)[i] : ((const int*)p)[i];
}
__device__ __forceinline__ int clampi(int v, int lo, int hi) {
    return min(max(v, lo), hi);
}

// ---------------------------------------------------------------------------
// CSR construction
// ---------------------------------------------------------------------------
__global__ void k_zero_counts(int* rowcnt, int* fillcnt, int N) {
    int i = blockIdx.x * blockDim.x + threadIdx.x;
    if (i < N) { rowcnt[i] = 0; fillcnt[i] = 0; }
}

__global__ void k_hist(const void* __restrict__ ei, int* rowcnt, int E, int N,
                       const int* __restrict__ flag64) {
    int e = blockIdx.x * blockDim.x + threadIdx.x;
    if (e >= E) return;
    int f = *flag64;
    int d = clampi(idx_at(ei, (size_t)E + e, f), 0, N - 1);
    atomicAdd(&rowcnt[d], 1);
}

// Single-block exclusive scan over rowcnt -> rowstart (N up to 50k).
__global__ __launch_bounds__(1024) void k_scan(const int* __restrict__ rowcnt,
                                               int* __restrict__ rowstart, int N) {
    __shared__ int warp_sums[32];
    __shared__ int s_carry;
    int tid = threadIdx.x, lane = tid & 31, warp = tid >> 5;
    if (tid == 0) s_carry = 0;
    __syncthreads();
    for (int base = 0; base < N; base += 1024) {
        int i = base + tid;
        int v = (i < N) ? rowcnt[i] : 0;
        int incl = v;
#pragma unroll
        for (int d = 1; d < 32; d <<= 1) {
            int t = __shfl_up_sync(0xffffffffu, incl, d);
            if (lane >= d) incl += t;
        }
        if (lane == 31) warp_sums[warp] = incl;
        __syncthreads();
        if (warp == 0) {
            int w = warp_sums[lane];
#pragma unroll
            for (int d = 1; d < 32; d <<= 1) {
                int t = __shfl_up_sync(0xffffffffu, w, d);
                if (lane >= d) w += t;
            }
            warp_sums[lane] = w;
        }
        __syncthreads();
        int warp_off = (warp == 0) ? 0 : warp_sums[warp - 1];
        int excl = s_carry + warp_off + incl - v;
        if (i < N) rowstart[i] = excl;
        __syncthreads();
        if (tid == 1023) s_carry += warp_sums[31];
        __syncthreads();
    }
    if (tid == 0) rowstart[N] = s_carry;
}

__global__ void k_fill(const void* __restrict__ ei,
                       const int* __restrict__ rowstart, int* fillcnt,
                       int* __restrict__ col, int E, int N,
                       const int* __restrict__ flag64) {
    int e = blockIdx.x * blockDim.x + threadIdx.x;
    if (e >= E) return;
    int f = *flag64;
    int s = clampi(idx_at(ei, e, f), 0, N - 1);
    int d = clampi(idx_at(ei, (size_t)E + e, f), 0, N - 1);
    int pos = rowstart[d] + atomicAdd(&fillcnt[d], 1);
    col[pos] = s;
}

__global__ void k_dinv(const int* __restrict__ rowcnt, float* dinv, int N) {
    int i = blockIdx.x * blockDim.x + threadIdx.x;
    if (i < N) dinv[i] = rsqrtf(1.0f + (float)rowcnt[i]);  // +1 self-loop
}

// ---------------------------------------------------------------------------
// GEMM: Y[N,128] = act(X)[N,128] @ W[128,128]
// act = relu(x + bprev) if bprev != nullptr (fuses previous layer's bias+relu)
// ---------------------------------------------------------------------------
#define GEMM_SMEM ((DD * DD + 64 * DD) * 4)

__global__ __launch_bounds__(256) void k_gemm(const float* __restrict__ X,
                                              const float* __restrict__ W,
                                              const float* __restrict__ bprev,
                                              float* __restrict__ Y, int N) {
    extern __shared__ float sm[];
    float* Wsm = sm;            // 128*128
    float* Rsm = sm + DD * DD;  // 64*128
    int tid  = threadIdx.x;
    int row0 = blockIdx.x * 64;

    {
        const float4* Wg  = (const float4*)W;
        float4*       Ws4 = (float4*)Wsm;
        for (int i = tid; i < DD * DD / 4; i += 256) Ws4[i] = Wg[i];
    }
    for (int e = tid; e < 64 * 32; e += 256) {
        int r = e >> 5, k4 = e & 31;
        int gr = row0 + r;
        float4 v = make_float4(0.f, 0.f, 0.f, 0.f);
        if (gr < N) v = ((const float4*)(X + (size_t)gr * DD))[k4];
        if (bprev) {
            float4 b = ((const float4*)bprev)[k4];
            v.x = fmaxf(v.x + b.x, 0.f);
            v.y = fmaxf(v.y + b.y, 0.f);
            v.z = fmaxf(v.z + b.z, 0.f);
            v.w = fmaxf(v.w + b.w, 0.f);
        }
        ((float4*)(Rsm + r * DD))[k4] = v;
    }
    __syncthreads();

    int warp = tid >> 5, lane = tid & 31;
    int r0 = warp * 8;
    float acc[8][4];
#pragma unroll
    for (int r = 0; r < 8; r++)
#pragma unroll
        for (int j = 0; j < 4; j++) acc[r][j] = 0.f;

#pragma unroll 2
    for (int k = 0; k < DD; k++) {
        float4 w = *(const float4*)(Wsm + k * DD + lane * 4);  // conflict-free LDS.128
#pragma unroll
        for (int r = 0; r < 8; r++) {
            float a = Rsm[(r0 + r) * DD + k];  // warp-broadcast LDS
            acc[r][0] += a * w.x;
            acc[r][1] += a * w.y;
            acc[r][2] += a * w.z;
            acc[r][3] += a * w.w;
        }
    }
#pragma unroll
    for (int r = 0; r < 8; r++) {
        int gr = row0 + r0 + r;
        if (gr < N)
            *(float4*)(Y + (size_t)gr * DD + lane * 4) =
                make_float4(acc[r][0], acc[r][1], acc[r][2], acc[r][3]);
    }
}

// ---------------------------------------------------------------------------
// CSR gather aggregation (fuses self-loop):
//   acc = t[n]*dinv[n]^2 + sum_{j in row n} t[col[j]] * dinv[col[j]]*dinv[n]
// Warp per node; lane owns 4 floats. No atomics on the feature table.
// If (pool_out == nullptr): agg[n] = acc.
// Else (final layer): red.add relu(acc + b3) into pool_out[batch[n]] and
// count nodes per graph — pooling fused, agg never materialized.
// ---------------------------------------------------------------------------
__global__ __launch_bounds__(256) void k_gather(const float* __restrict__ t,
                                                const int* __restrict__ rowstart,
                                                const int* __restrict__ col,
                                                const float* __restrict__ dinv,
                                                float* __restrict__ agg,
                                                float* __restrict__ pool_out,
                                                const float* __restrict__ b3,
                                                const void* __restrict__ batch,
                                                float* __restrict__ cnt,
                                                const int* __restrict__ flag64,
                                                int N, int G) {
    int g = blockIdx.x * blockDim.x + threadIdx.x;
    int n = g >> 5, lane = g & 31;
    if (n >= N) return;

    float cd = dinv[n];
    int jb = rowstart[n];
    int je = rowstart[n + 1];

    // self-loop term
    float4 a = ((const float4*)(t + (size_t)n * DD))[lane];
    float c0 = cd * cd;
    float4 acc = make_float4(a.x * c0, a.y * c0, a.z * c0, a.w * c0);

#pragma unroll 2
    for (int j = jb; j < je; j++) {
        int s = col[j];                       // warp-broadcast L1 hit
        float c = dinv[s] * cd;
        float4 v = ((const float4*)(t + (size_t)s * DD))[lane];  // coalesced 512B/warp
        acc.x += v.x * c;
        acc.y += v.y * c;
        acc.z += v.z * c;
        acc.w += v.w * c;
    }

    if (pool_out == nullptr) {
        ((float4*)(agg + (size_t)n * DD))[lane] = acc;
    } else {
        float4 b = ((const float4*)b3)[lane];
        acc.x = fmaxf(acc.x + b.x, 0.f);
        acc.y = fmaxf(acc.y + b.y, 0.f);
        acc.z = fmaxf(acc.z + b.z, 0.f);
        acc.w = fmaxf(acc.w + b.w, 0.f);
        int f = *flag64;
        int gid = clampi(idx_at(batch, n, f), 0, G - 1);
        float* p = pool_out + (size_t)gid * DD + lane * 4;
        asm volatile("red.global.add.v4.f32 [%0], {%1, %2, %3, %4};" ::
                     "l"(p), "f"(acc.x), "f"(acc.y), "f"(acc.z), "f"(acc.w)
                     : "memory");
        if (lane == 0) atomicAdd(&cnt[gid], 1.0f);
    }
}

// ---------------------------------------------------------------------------
// Pooling epilogue
// ---------------------------------------------------------------------------
__global__ void k_pool_zero(float* __restrict__ out, float* __restrict__ cnt, int G) {
    int i = blockIdx.x * blockDim.x + threadIdx.x;
    if (i < G * DD) out[i] = 0.f;
    if (i < G) cnt[i] = 0.f;
}

__global__ void k_pool_div(float* __restrict__ out, const float* __restrict__ cnt, int G) {
    int i = blockIdx.x * blockDim.x + threadIdx.x;
    if (i < G * DD) out[i] /= fmaxf(cnt[i >> 7], 1.0f);
}

// ---------------------------------------------------------------------------
extern "C" void kernel_launch(void* const* d_in, const int* in_sizes, int n_in,
                              void* d_out, int out_size) {
    const float* x     = (const float*)d_in[0];
    // d_in[1] = edge_attr (unused by GCNConv)
    const float* W1    = (const float*)d_in[2];
    const float* b1    = (const float*)d_in[3];
    const float* W2    = (const float*)d_in[4];
    const float* b2    = (const float*)d_in[5];
    const float* W3    = (const float*)d_in[6];
    const float* b3    = (const float*)d_in[7];
    const void*  ei    = d_in[8];
    const void*  batch = d_in[9];
    float*       out   = (float*)d_out;

    int N = in_sizes[0] / DD;
    int E = in_sizes[8] / 2;
    int G = out_size / DD;

    cudaFuncSetAttribute(k_gemm, cudaFuncAttributeMaxDynamicSharedMemorySize, GEMM_SMEM);

    void *pDinv, *pA, *pB, *pC, *pCnt, *pRC, *pFC, *pRS, *pCol, *pF64;
    cudaGetSymbolAddress(&pDinv, g_dinv);
    cudaGetSymbolAddress(&pA,    g_bufA);
    cudaGetSymbolAddress(&pB,    g_bufB);
    cudaGetSymbolAddress(&pC,    g_bufC);
    cudaGetSymbolAddress(&pCnt,  g_cnt);
    cudaGetSymbolAddress(&pRC,   g_rowcnt);
    cudaGetSymbolAddress(&pFC,   g_fillcnt);
    cudaGetSymbolAddress(&pRS,   g_rowstart);
    cudaGetSymbolAddress(&pCol,  g_col);
    cudaGetSymbolAddress(&pF64,  g_is64);
    float* dinv = (float*)pDinv;
    float* A    = (float*)pA;
    float* B    = (float*)pB;
    float* C    = (float*)pC;
    float* cnt  = (float*)pCnt;
    int* rowcnt   = (int*)pRC;
    int* fillcnt  = (int*)pFC;
    int* rowstart = (int*)pRS;
    int* col      = (int*)pCol;
    int* flag64   = (int*)pF64;

    int gemm_blocks      = (N + 63) / 64;
    int nthread_blocks   = (N + 255) / 256;
    int edge_blocks      = (E + 255) / 256;
    int node_warp_blocks = (int)(((size_t)N * 32 + 255) / 256);  // warp per node

    // --- dtype detection + CSR build + normalization ---
    k_detect<<<1, 256>>>((const int*)ei, 2048, flag64);
    k_zero_counts<<<nthread_blocks, 256>>>(rowcnt, fillcnt, N);
    k_hist<<<edge_blocks, 256>>>(ei, rowcnt, E, N, flag64);
    k_scan<<<1, 1024>>>(rowcnt, rowstart, N);
    k_fill<<<edge_blocks, 256>>>(ei, rowstart, fillcnt, col, E, N, flag64);
    k_dinv<<<nthread_blocks, 256>>>(rowcnt, dinv, N);

    // Layer 1: t = x@W1 ; agg1(B) = gather(t)
    k_gemm<<<gemm_blocks, 256, GEMM_SMEM>>>(x, W1, nullptr, A, N);
    k_gather<<<node_warp_blocks, 256>>>(A, rowstart, col, dinv, B,
                                        nullptr, nullptr, nullptr, nullptr, flag64, N, G);

    // Layer 2: t = relu(agg1+b1)@W2 ; agg2(C)
    k_gemm<<<gemm_blocks, 256, GEMM_SMEM>>>(B, W2, b1, A, N);
    k_gather<<<node_warp_blocks, 256>>>(A, rowstart, col, dinv, C,
                                        nullptr, nullptr, nullptr, nullptr, flag64, N, G);

    // Layer 3 + fused pool: t = relu(agg2+b2)@W3 ; out += relu(gather(t)+b3) per graph
    k_gemm<<<gemm_blocks, 256, GEMM_SMEM>>>(C, W3, b2, A, N);
    k_pool_zero<<<(G * DD + 255) / 256, 256>>>(out, cnt, G);
    k_gather<<<node_warp_blocks, 256>>>(A, rowstart, col, dinv, nullptr,
                                        out, b3, batch, cnt, flag64, N, G);

    k_pool_div<<<(G * DD + 255) / 256, 256>>>(out, cnt, G);
}

// round 15
// speedup vs baseline: 1.0536x; 1.0536x over previous
#include <cuda_runtime.h>
#include <cuda_bf16.h>
#include <cstdint>

#define NMAX 50000
#define EMAX 800000
#define DD   128
#define GMAX 512

// Scratch (no allocation allowed; __device__ globals are the sanctioned path).
__device__ __align__(16) float g_dinv[NMAX];
__device__ __align__(16) float g_bufA[(size_t)NMAX * DD];
__device__ __align__(16) float g_bufB[(size_t)NMAX * DD];
__device__ __align__(16) float g_bufC[(size_t)NMAX * DD];
__device__ __align__(16) float g_cnt[GMAX];
// CSR scratch
__device__ __align__(16) int g_rowcnt[NMAX];
__device__ __align__(16) int g_fillcnt[NMAX];
__device__ __align__(16) int g_rowstart[NMAX];
__device__ __align__(16) int g_col[EMAX];
__device__ int g_cursor;   // segment allocation cursor
__device__ int g_is64;     // 1 if integer inputs are int64, 0 if int32

// ---------------------------------------------------------------------------
// Dtype detection: if edge_index is int64 (values < 2^31, nonneg), every odd
// int32 word is 0. Sample the first 2048 elements (16KB — in bounds whether
// the buffer is 6.4MB int32 or 12.8MB int64).
// ---------------------------------------------------------------------------
__global__ void k_detect(const int* __restrict__ p, int nSample, int* flag64) {
    __shared__ int s_any;
    if (threadIdx.x == 0) s_any = 0;
    __syncthreads();
    int acc = 0;
    for (int k = threadIdx.x; k < nSample; k += blockDim.x) acc |= p[2 * k + 1];
    if (acc) atomicOr(&s_any, 1);
    __syncthreads();
    if (threadIdx.x == 0) *flag64 = (s_any == 0) ? 1 : 0;
}

__device__ __forceinline__ int idx_at(const void* p, size_t i, int f64) {
    return f64 ? (int)((const long long*)p)[i] : ((const int*)p)[i];
}
__device__ __forceinline__ int clampi(int v, int lo, int hi) {
    return min(max(v, lo), hi);
}

// ---------------------------------------------------------------------------
// CSR construction (scan-free)
// ---------------------------------------------------------------------------
__global__ void k_zero_counts(int* rowcnt, int* fillcnt, int* cursor, int N) {
    int i = blockIdx.x * blockDim.x + threadIdx.x;
    if (i < N) { rowcnt[i] = 0; fillcnt[i] = 0; }
    if (i == 0) *cursor = 0;
}

__global__ void k_hist(const void* __restrict__ ei, int* rowcnt, int E, int N,
                       const int* __restrict__ flag64) {
    int e = blockIdx.x * blockDim.x + threadIdx.x;
    if (e >= E) return;
    int f = *flag64;
    int d = clampi(idx_at(ei, (size_t)E + e, f), 0, N - 1);
    atomicAdd(&rowcnt[d], 1);
}

// Order-free segment allocation: warp-aggregated atomicAdd on a global cursor.
// Each node n gets a contiguous [rowstart[n], rowstart[n]+rowcnt[n]) segment
// (segment order across nodes is arbitrary — gather only needs contiguity).
// Also fuses dinv[n] = rsqrt(1 + rowcnt[n]).
__global__ void k_alloc(const int* __restrict__ rowcnt, int* __restrict__ rowstart,
                        float* __restrict__ dinv, int* cursor, int N) {
    int i = blockIdx.x * blockDim.x + threadIdx.x;
    int lane = threadIdx.x & 31;
    int v = (i < N) ? rowcnt[i] : 0;
    int incl = v;
#pragma unroll
    for (int d = 1; d < 32; d <<= 1) {
        int t = __shfl_up_sync(0xffffffffu, incl, d);
        if (lane >= d) incl += t;
    }
    int total = __shfl_sync(0xffffffffu, incl, 31);
    int base = 0;
    if (lane == 0 && total > 0) base = atomicAdd(cursor, total);
    base = __shfl_sync(0xffffffffu, base, 0);
    if (i < N) {
        rowstart[i] = base + incl - v;
        dinv[i] = rsqrtf(1.0f + (float)v);
    }
}

__global__ void k_fill(const void* __restrict__ ei,
                       const int* __restrict__ rowstart, int* fillcnt,
                       int* __restrict__ col, int E, int N,
                       const int* __restrict__ flag64) {
    int e = blockIdx.x * blockDim.x + threadIdx.x;
    if (e >= E) return;
    int f = *flag64;
    int s = clampi(idx_at(ei, e, f), 0, N - 1);
    int d = clampi(idx_at(ei, (size_t)E + e, f), 0, N - 1);
    int pos = rowstart[d] + atomicAdd(&fillcnt[d], 1);
    col[pos] = s;
}

// ---------------------------------------------------------------------------
// GEMM: Y[N,128] = act(X)[N,128] @ W[128,128]
// act = relu(x + bprev) if bprev != nullptr (fuses previous layer's bias+relu)
// ---------------------------------------------------------------------------
#define GEMM_SMEM ((DD * DD + 64 * DD) * 4)

__global__ __launch_bounds__(256) void k_gemm(const float* __restrict__ X,
                                              const float* __restrict__ W,
                                              const float* __restrict__ bprev,
                                              float* __restrict__ Y, int N) {
    extern __shared__ float sm[];
    float* Wsm = sm;            // 128*128
    float* Rsm = sm + DD * DD;  // 64*128
    int tid  = threadIdx.x;
    int row0 = blockIdx.x * 64;

    {
        const float4* Wg  = (const float4*)W;
        float4*       Ws4 = (float4*)Wsm;
        for (int i = tid; i < DD * DD / 4; i += 256) Ws4[i] = Wg[i];
    }
    for (int e = tid; e < 64 * 32; e += 256) {
        int r = e >> 5, k4 = e & 31;
        int gr = row0 + r;
        float4 v = make_float4(0.f, 0.f, 0.f, 0.f);
        if (gr < N) v = ((const float4*)(X + (size_t)gr * DD))[k4];
        if (bprev) {
            float4 b = ((const float4*)bprev)[k4];
            v.x = fmaxf(v.x + b.x, 0.f);
            v.y = fmaxf(v.y + b.y, 0.f);
            v.z = fmaxf(v.z + b.z, 0.f);
            v.w = fmaxf(v.w + b.w, 0.f);
        }
        ((float4*)(Rsm + r * DD))[k4] = v;
    }
    __syncthreads();

    int warp = tid >> 5, lane = tid & 31;
    int r0 = warp * 8;
    float acc[8][4];
#pragma unroll
    for (int r = 0; r < 8; r++)
#pragma unroll
        for (int j = 0; j < 4; j++) acc[r][j] = 0.f;

#pragma unroll 2
    for (int k = 0; k < DD; k++) {
        float4 w = *(const float4*)(Wsm + k * DD + lane * 4);  // conflict-free LDS.128
#pragma unroll
        for (int r = 0; r < 8; r++) {
            float a = Rsm[(r0 + r) * DD + k];  // warp-broadcast LDS
            acc[r][0] += a * w.x;
            acc[r][1] += a * w.y;
            acc[r][2] += a * w.z;
            acc[r][3] += a * w.w;
        }
    }
#pragma unroll
    for (int r = 0; r < 8; r++) {
        int gr = row0 + r0 + r;
        if (gr < N)
            *(float4*)(Y + (size_t)gr * DD + lane * 4) =
                make_float4(acc[r][0], acc[r][1], acc[r][2], acc[r][3]);
    }
}

// ---------------------------------------------------------------------------
// CSR gather aggregation (fuses self-loop):
//   acc = t[n]*dinv[n]^2 + sum_{j in seg n} t[col[j]] * dinv[col[j]]*dinv[n]
// Warp per node; lane owns 4 floats.
// Index batching: per 32-neighbor chunk, lane L loads col[base+L] and its dinv
// (coalesced), then the loop reads both via SHFL — the only memory op per
// iteration is the payload LDG.128, which pipelines freely.
// If (pool_out == nullptr): agg[n] = acc.
// Else (final layer): red.add relu(acc + b3) into pool_out[batch[n]].
// ---------------------------------------------------------------------------
__global__ __launch_bounds__(256) void k_gather(const float* __restrict__ t,
                                                const int* __restrict__ rowstart,
                                                const int* __restrict__ rowcnt,
                                                const int* __restrict__ col,
                                                const float* __restrict__ dinv,
                                                float* __restrict__ agg,
                                                float* __restrict__ pool_out,
                                                const float* __restrict__ b3,
                                                const void* __restrict__ batch,
                                                float* __restrict__ cnt,
                                                const int* __restrict__ flag64,
                                                int N, int G) {
    int g = blockIdx.x * blockDim.x + threadIdx.x;
    int n = g >> 5, lane = g & 31;
    if (n >= N) return;

    float cd = dinv[n];
    int jb = rowstart[n];
    int deg = rowcnt[n];

    // self-loop term
    float4 a = ((const float4*)(t + (size_t)n * DD))[lane];
    float c0 = cd * cd;
    float4 acc = make_float4(a.x * c0, a.y * c0, a.z * c0, a.w * c0);

    for (int base = 0; base < deg; base += 32) {
        int m = deg - base;             // neighbors in this chunk (may be >32)
        int cntc = min(m, 32);
        int myS = 0; float myC = 0.f;
        if (lane < cntc) {
            myS = col[jb + base + lane];   // coalesced chunk load
            myC = dinv[myS] * cd;          // per-lane coefficient
        }
        for (int k = 0; k < cntc; k++) {
            int   s = __shfl_sync(0xffffffffu, myS, k);
            float c = __shfl_sync(0xffffffffu, myC, k);
            float4 v = ((const float4*)(t + (size_t)s * DD))[lane];  // coalesced 512B/warp
            acc.x += v.x * c;
            acc.y += v.y * c;
            acc.z += v.z * c;
            acc.w += v.w * c;
        }
    }

    if (pool_out == nullptr) {
        ((float4*)(agg + (size_t)n * DD))[lane] = acc;
    } else {
        float4 b = ((const float4*)b3)[lane];
        acc.x = fmaxf(acc.x + b.x, 0.f);
        acc.y = fmaxf(acc.y + b.y, 0.f);
        acc.z = fmaxf(acc.z + b.z, 0.f);
        acc.w = fmaxf(acc.w + b.w, 0.f);
        int f = *flag64;
        int gid = clampi(idx_at(batch, n, f), 0, G - 1);
        float* p = pool_out + (size_t)gid * DD + lane * 4;
        asm volatile("red.global.add.v4.f32 [%0], {%1, %2, %3, %4};" ::
                     "l"(p), "f"(acc.x), "f"(acc.y), "f"(acc.z), "f"(acc.w)
                     : "memory");
        if (lane == 0) atomicAdd(&cnt[gid], 1.0f);
    }
}

// ---------------------------------------------------------------------------
// Pooling epilogue
// ---------------------------------------------------------------------------
__global__ void k_pool_zero(float* __restrict__ out, float* __restrict__ cnt, int G) {
    int i = blockIdx.x * blockDim.x + threadIdx.x;
    if (i < G * DD) out[i] = 0.f;
    if (i < G) cnt[i] = 0.f;
}

__global__ void k_pool_div(float* __restrict__ out, const float* __restrict__ cnt, int G) {
    int i = blockIdx.x * blockDim.x + threadIdx.x;
    if (i < G * DD) out[i] /= fmaxf(cnt[i >> 7], 1.0f);
}

// ---------------------------------------------------------------------------
extern "C" void kernel_launch(void* const* d_in, const int* in_sizes, int n_in,
                              void* d_out, int out_size) {
    const float* x     = (const float*)d_in[0];
    // d_in[1] = edge_attr (unused by GCNConv)
    const float* W1    = (const float*)d_in[2];
    const float* b1    = (const float*)d_in[3];
    const float* W2    = (const float*)d_in[4];
    const float* b2    = (const float*)d_in[5];
    const float* W3    = (const float*)d_in[6];
    const float* b3    = (const float*)d_in[7];
    const void*  ei    = d_in[8];
    const void*  batch = d_in[9];
    float*       out   = (float*)d_out;

    int N = in_sizes[0] / DD;
    int E = in_sizes[8] / 2;
    int G = out_size / DD;

    cudaFuncSetAttribute(k_gemm, cudaFuncAttributeMaxDynamicSharedMemorySize, GEMM_SMEM);

    void *pDinv, *pA, *pB, *pC, *pCnt, *pRC, *pFC, *pRS, *pCol, *pCur, *pF64;
    cudaGetSymbolAddress(&pDinv, g_dinv);
    cudaGetSymbolAddress(&pA,    g_bufA);
    cudaGetSymbolAddress(&pB,    g_bufB);
    cudaGetSymbolAddress(&pC,    g_bufC);
    cudaGetSymbolAddress(&pCnt,  g_cnt);
    cudaGetSymbolAddress(&pRC,   g_rowcnt);
    cudaGetSymbolAddress(&pFC,   g_fillcnt);
    cudaGetSymbolAddress(&pRS,   g_rowstart);
    cudaGetSymbolAddress(&pCol,  g_col);
    cudaGetSymbolAddress(&pCur,  g_cursor);
    cudaGetSymbolAddress(&pF64,  g_is64);
    float* dinv = (float*)pDinv;
    float* A    = (float*)pA;
    float* B    = (float*)pB;
    float* C    = (float*)pC;
    float* cnt  = (float*)pCnt;
    int* rowcnt   = (int*)pRC;
    int* fillcnt  = (int*)pFC;
    int* rowstart = (int*)pRS;
    int* col      = (int*)pCol;
    int* cursor   = (int*)pCur;
    int* flag64   = (int*)pF64;

    int gemm_blocks      = (N + 63) / 64;
    int nthread_blocks   = (N + 255) / 256;
    int edge_blocks      = (E + 255) / 256;
    int node_warp_blocks = (int)(((size_t)N * 32 + 255) / 256);  // warp per node

    // --- dtype detection + CSR build (scan-free) + normalization ---
    k_detect<<<1, 256>>>((const int*)ei, 2048, flag64);
    k_zero_counts<<<nthread_blocks, 256>>>(rowcnt, fillcnt, cursor, N);
    k_hist<<<edge_blocks, 256>>>(ei, rowcnt, E, N, flag64);
    k_alloc<<<nthread_blocks, 256>>>(rowcnt, rowstart, dinv, cursor, N);
    k_fill<<<edge_blocks, 256>>>(ei, rowstart, fillcnt, col, E, N, flag64);

    // Layer 1: t = x@W1 ; agg1(B) = gather(t)
    k_gemm<<<gemm_blocks, 256, GEMM_SMEM>>>(x, W1, nullptr, A, N);
    k_gather<<<node_warp_blocks, 256>>>(A, rowstart, rowcnt, col, dinv, B,
                                        nullptr, nullptr, nullptr, nullptr, flag64, N, G);

    // Layer 2: t = relu(agg1+b1)@W2 ; agg2(C)
    k_gemm<<<gemm_blocks, 256, GEMM_SMEM>>>(B, W2, b1, A, N);
    k_gather<<<node_warp_blocks, 256>>>(A, rowstart, rowcnt, col, dinv, C,
                                        nullptr, nullptr, nullptr, nullptr, flag64, N, G);

    // Layer 3 + fused pool: t = relu(agg2+b2)@W3 ; out += relu(gather(t)+b3) per graph
    k_gemm<<<gemm_blocks, 256, GEMM_SMEM>>>(C, W3, b2, A, N);
    k_pool_zero<<<(G * DD + 255) / 256, 256>>>(out, cnt, G);
    k_gather<<<node_warp_blocks, 256>>>(A, rowstart, rowcnt, col, dinv, nullptr,
                                        out, b3, batch, cnt, flag64, N, G);

    k_pool_div<<<(G * DD + 255) / 256, 256>>>(out, cnt, G);
}

// round 17
// speedup vs baseline: 1.1014x; 1.0453x over previous
#include <cuda_runtime.h>
#include <cuda_bf16.h>
#include <cstdint>

#define NMAX 50000
#define EMAX 800000
#define DD   128
#define GMAX 512

// Scratch (no allocation allowed; __device__ globals are the sanctioned path).
__device__ __align__(16) float g_dinv[NMAX];
__device__ __align__(16) float g_bufA[(size_t)NMAX * DD];
__device__ __align__(16) float g_bufB[(size_t)NMAX * DD];
__device__ __align__(16) float g_bufC[(size_t)NMAX * DD];
__device__ __align__(16) float g_cnt[GMAX];
// CSR scratch
__device__ __align__(16) int g_rowcnt[NMAX];
__device__ __align__(16) int g_fillcnt[NMAX];
__device__ __align__(16) int g_rowstart[NMAX];
__device__ __align__(16) int g_col[EMAX];
__device__ int g_cursor;   // segment allocation cursor
__device__ int g_is64;     // 1 if integer inputs are int64, 0 if int32

// ---------------------------------------------------------------------------
// Dtype detection: if edge_index is int64 (values < 2^31, nonneg), every odd
// int32 word is 0. Sample the first 2048 elements (16KB — in bounds whether
// the buffer is 6.4MB int32 or 12.8MB int64).
// ---------------------------------------------------------------------------
__global__ void k_detect(const int* __restrict__ p, int nSample, int* flag64) {
    __shared__ int s_any;
    if (threadIdx.x == 0) s_any = 0;
    __syncthreads();
    int acc = 0;
    for (int k = threadIdx.x; k < nSample; k += blockDim.x) acc |= p[2 * k + 1];
    if (acc) atomicOr(&s_any, 1);
    __syncthreads();
    if (threadIdx.x == 0) *flag64 = (s_any == 0) ? 1 : 0;
}

__device__ __forceinline__ int idx_at(const void* p, size_t i, int f64) {
    return f64 ? (int)((const long long*)p)[i] : ((const int*)p)[i];
}
__device__ __forceinline__ int clampi(int v, int lo, int hi) {
    return min(max(v, lo), hi);
}

// ---------------------------------------------------------------------------
// CSR construction (scan-free)
// ---------------------------------------------------------------------------
__global__ void k_zero_counts(int* rowcnt, int* fillcnt, int* cursor, int N) {
    int i = blockIdx.x * blockDim.x + threadIdx.x;
    if (i < N) { rowcnt[i] = 0; fillcnt[i] = 0; }
    if (i == 0) *cursor = 0;
}

__global__ void k_hist(const void* __restrict__ ei, int* rowcnt, int E, int N,
                       const int* __restrict__ flag64) {
    int e = blockIdx.x * blockDim.x + threadIdx.x;
    if (e >= E) return;
    int f = *flag64;
    int d = clampi(idx_at(ei, (size_t)E + e, f), 0, N - 1);
    atomicAdd(&rowcnt[d], 1);
}

// Order-free segment allocation: warp-aggregated atomicAdd on a global cursor.
// Each node n gets a contiguous [rowstart[n], rowstart[n]+rowcnt[n]) segment
// (segment order across nodes is arbitrary — gather only needs contiguity).
// Also fuses dinv[n] = rsqrt(1 + rowcnt[n]).
__global__ void k_alloc(const int* __restrict__ rowcnt, int* __restrict__ rowstart,
                        float* __restrict__ dinv, int* cursor, int N) {
    int i = blockIdx.x * blockDim.x + threadIdx.x;
    int lane = threadIdx.x & 31;
    int v = (i < N) ? rowcnt[i] : 0;
    int incl = v;
#pragma unroll
    for (int d = 1; d < 32; d <<= 1) {
        int t = __shfl_up_sync(0xffffffffu, incl, d);
        if (lane >= d) incl += t;
    }
    int total = __shfl_sync(0xffffffffu, incl, 31);
    int base = 0;
    if (lane == 0 && total > 0) base = atomicAdd(cursor, total);
    base = __shfl_sync(0xffffffffu, base, 0);
    if (i < N) {
        rowstart[i] = base + incl - v;
        dinv[i] = rsqrtf(1.0f + (float)v);
    }
}

__global__ void k_fill(const void* __restrict__ ei,
                       const int* __restrict__ rowstart, int* fillcnt,
                       int* __restrict__ col, int E, int N,
                       const int* __restrict__ flag64) {
    int e = blockIdx.x * blockDim.x + threadIdx.x;
    if (e >= E) return;
    int f = *flag64;
    int s = clampi(idx_at(ei, e, f), 0, N - 1);
    int d = clampi(idx_at(ei, (size_t)E + e, f), 0, N - 1);
    int pos = rowstart[d] + atomicAdd(&fillcnt[d], 1);
    col[pos] = s;
}

// ---------------------------------------------------------------------------
// GEMM: Y[N,128] = act(X)[N,128] @ W[128,128]
// act = relu(x + bprev) if bprev != nullptr (fuses previous layer's bias+relu)
// ---------------------------------------------------------------------------
#define GEMM_SMEM ((DD * DD + 64 * DD) * 4)

__global__ __launch_bounds__(256) void k_gemm(const float* __restrict__ X,
                                              const float* __restrict__ W,
                                              const float* __restrict__ bprev,
                                              float* __restrict__ Y, int N) {
    extern __shared__ float sm[];
    float* Wsm = sm;            // 128*128
    float* Rsm = sm + DD * DD;  // 64*128
    int tid  = threadIdx.x;
    int row0 = blockIdx.x * 64;

    {
        const float4* Wg  = (const float4*)W;
        float4*       Ws4 = (float4*)Wsm;
        for (int i = tid; i < DD * DD / 4; i += 256) Ws4[i] = Wg[i];
    }
    for (int e = tid; e < 64 * 32; e += 256) {
        int r = e >> 5, k4 = e & 31;
        int gr = row0 + r;
        float4 v = make_float4(0.f, 0.f, 0.f, 0.f);
        if (gr < N) v = ((const float4*)(X + (size_t)gr * DD))[k4];
        if (bprev) {
            float4 b = ((const float4*)bprev)[k4];
            v.x = fmaxf(v.x + b.x, 0.f);
            v.y = fmaxf(v.y + b.y, 0.f);
            v.z = fmaxf(v.z + b.z, 0.f);
            v.w = fmaxf(v.w + b.w, 0.f);
        }
        ((float4*)(Rsm + r * DD))[k4] = v;
    }
    __syncthreads();

    int warp = tid >> 5, lane = tid & 31;
    int r0 = warp * 8;
    float acc[8][4];
#pragma unroll
    for (int r = 0; r < 8; r++)
#pragma unroll
        for (int j = 0; j < 4; j++) acc[r][j] = 0.f;

#pragma unroll 2
    for (int k = 0; k < DD; k++) {
        float4 w = *(const float4*)(Wsm + k * DD + lane * 4);  // conflict-free LDS.128
#pragma unroll
        for (int r = 0; r < 8; r++) {
            float a = Rsm[(r0 + r) * DD + k];  // warp-broadcast LDS
            acc[r][0] += a * w.x;
            acc[r][1] += a * w.y;
            acc[r][2] += a * w.z;
            acc[r][3] += a * w.w;
        }
    }
#pragma unroll
    for (int r = 0; r < 8; r++) {
        int gr = row0 + r0 + r;
        if (gr < N)
            *(float4*)(Y + (size_t)gr * DD + lane * 4) =
                make_float4(acc[r][0], acc[r][1], acc[r][2], acc[r][3]);
    }
}

// ---------------------------------------------------------------------------
// CSR gather aggregation (fuses self-loop):
//   acc = t[n]*dinv[n]^2 + sum_{j in seg n} t[col[j]] * dinv[col[j]]*dinv[n]
// Warp per node; lane owns 4 floats. Simple per-iteration broadcast loads of
// col[j]/dinv[s] (L1-hit, scoreboard-pipelined) — measured faster than SHFL
// batching (SHFL lat 26-32cyc serialized on the FMA path; R15 post-mortem).
// If (pool_out == nullptr): agg[n] = acc.
// Else (final layer): red.add relu(acc + b3) into pool_out[batch[n]].
// ---------------------------------------------------------------------------
__global__ __launch_bounds__(256) void k_gather(const float* __restrict__ t,
                                                const int* __restrict__ rowstart,
                                                const int* __restrict__ rowcnt,
                                                const int* __restrict__ col,
                                                const float* __restrict__ dinv,
                                                float* __restrict__ agg,
                                                float* __restrict__ pool_out,
                                                const float* __restrict__ b3,
                                                const void* __restrict__ batch,
                                                float* __restrict__ cnt,
                                                const int* __restrict__ flag64,
                                                int N, int G) {
    int g = blockIdx.x * blockDim.x + threadIdx.x;
    int n = g >> 5, lane = g & 31;
    if (n >= N) return;

    float cd = dinv[n];
    int jb = rowstart[n];
    int je = jb + rowcnt[n];

    // self-loop term
    float4 a = ((const float4*)(t + (size_t)n * DD))[lane];
    float c0 = cd * cd;
    float4 acc = make_float4(a.x * c0, a.y * c0, a.z * c0, a.w * c0);

#pragma unroll 2
    for (int j = jb; j < je; j++) {
        int s = col[j];                       // warp-broadcast L1 hit
        float c = dinv[s] * cd;
        float4 v = ((const float4*)(t + (size_t)s * DD))[lane];  // coalesced 512B/warp
        acc.x += v.x * c;
        acc.y += v.y * c;
        acc.z += v.z * c;
        acc.w += v.w * c;
    }

    if (pool_out == nullptr) {
        ((float4*)(agg + (size_t)n * DD))[lane] = acc;
    } else {
        float4 b = ((const float4*)b3)[lane];
        acc.x = fmaxf(acc.x + b.x, 0.f);
        acc.y = fmaxf(acc.y + b.y, 0.f);
        acc.z = fmaxf(acc.z + b.z, 0.f);
        acc.w = fmaxf(acc.w + b.w, 0.f);
        int f = *flag64;
        int gid = clampi(idx_at(batch, n, f), 0, G - 1);
        float* p = pool_out + (size_t)gid * DD + lane * 4;
        asm volatile("red.global.add.v4.f32 [%0], {%1, %2, %3, %4};" ::
                     "l"(p), "f"(acc.x), "f"(acc.y), "f"(acc.z), "f"(acc.w)
                     : "memory");
        if (lane == 0) atomicAdd(&cnt[gid], 1.0f);
    }
}

// ---------------------------------------------------------------------------
// Pooling epilogue
// ---------------------------------------------------------------------------
__global__ void k_pool_zero(float* __restrict__ out, float* __restrict__ cnt, int G) {
    int i = blockIdx.x * blockDim.x + threadIdx.x;
    if (i < G * DD) out[i] = 0.f;
    if (i < G) cnt[i] = 0.f;
}

__global__ void k_pool_div(float* __restrict__ out, const float* __restrict__ cnt, int G) {
    int i = blockIdx.x * blockDim.x + threadIdx.x;
    if (i < G * DD) out[i] /= fmaxf(cnt[i >> 7], 1.0f);
}

// ---------------------------------------------------------------------------
extern "C" void kernel_launch(void* const* d_in, const int* in_sizes, int n_in,
                              void* d_out, int out_size) {
    const float* x     = (const float*)d_in[0];
    // d_in[1] = edge_attr (unused by GCNConv)
    const float* W1    = (const float*)d_in[2];
    const float* b1    = (const float*)d_in[3];
    const float* W2    = (const float*)d_in[4];
    const float* b2    = (const float*)d_in[5];
    const float* W3    = (const float*)d_in[6];
    const float* b3    = (const float*)d_in[7];
    const void*  ei    = d_in[8];
    const void*  batch = d_in[9];
    float*       out   = (float*)d_out;

    int N = in_sizes[0] / DD;
    int E = in_sizes[8] / 2;
    int G = out_size / DD;

    cudaFuncSetAttribute(k_gemm, cudaFuncAttributeMaxDynamicSharedMemorySize, GEMM_SMEM);

    void *pDinv, *pA, *pB, *pC, *pCnt, *pRC, *pFC, *pRS, *pCol, *pCur, *pF64;
    cudaGetSymbolAddress(&pDinv, g_dinv);
    cudaGetSymbolAddress(&pA,    g_bufA);
    cudaGetSymbolAddress(&pB,    g_bufB);
    cudaGetSymbolAddress(&pC,    g_bufC);
    cudaGetSymbolAddress(&pCnt,  g_cnt);
    cudaGetSymbolAddress(&pRC,   g_rowcnt);
    cudaGetSymbolAddress(&pFC,   g_fillcnt);
    cudaGetSymbolAddress(&pRS,   g_rowstart);
    cudaGetSymbolAddress(&pCol,  g_col);
    cudaGetSymbolAddress(&pCur,  g_cursor);
    cudaGetSymbolAddress(&pF64,  g_is64);
    float* dinv = (float*)pDinv;
    float* A    = (float*)pA;
    float* B    = (float*)pB;
    float* C    = (float*)pC;
    float* cnt  = (float*)pCnt;
    int* rowcnt   = (int*)pRC;
    int* fillcnt  = (int*)pFC;
    int* rowstart = (int*)pRS;
    int* col      = (int*)pCol;
    int* cursor   = (int*)pCur;
    int* flag64   = (int*)pF64;

    int gemm_blocks      = (N + 63) / 64;
    int nthread_blocks   = (N + 255) / 256;
    int edge_blocks      = (E + 255) / 256;
    int node_warp_blocks = (int)(((size_t)N * 32 + 255) / 256);  // warp per node

    // --- dtype detection + CSR build (scan-free) + normalization ---
    k_detect<<<1, 256>>>((const int*)ei, 2048, flag64);
    k_zero_counts<<<nthread_blocks, 256>>>(rowcnt, fillcnt, cursor, N);
    k_hist<<<edge_blocks, 256>>>(ei, rowcnt, E, N, flag64);
    k_alloc<<<nthread_blocks, 256>>>(rowcnt, rowstart, dinv, cursor, N);
    k_fill<<<edge_blocks, 256>>>(ei, rowstart, fillcnt, col, E, N, flag64);

    // Layer 1: t = x@W1 ; agg1(B) = gather(t)
    k_gemm<<<gemm_blocks, 256, GEMM_SMEM>>>(x, W1, nullptr, A, N);
    k_gather<<<node_warp_blocks, 256>>>(A, rowstart, rowcnt, col, dinv, B,
                                        nullptr, nullptr, nullptr, nullptr, flag64, N, G);

    // Layer 2: t = relu(agg1+b1)@W2 ; agg2(C)
    k_gemm<<<gemm_blocks, 256, GEMM_SMEM>>>(B, W2, b1, A, N);
    k_gather<<<node_warp_blocks, 256>>>(A, rowstart, rowcnt, col, dinv, C,
                                        nullptr, nullptr, nullptr, nullptr, flag64, N, G);

    // Layer 3 + fused pool: t = relu(agg2+b2)@W3 ; out += relu(gather(t)+b3) per graph
    k_gemm<<<gemm_blocks, 256, GEMM_SMEM>>>(C, W3, b2, A, N);
    k_pool_zero<<<(G * DD + 255) / 256, 256>>>(out, cnt, G);
    k_gather<<<node_warp_blocks, 256>>>(A, rowstart, rowcnt, col, dinv, nullptr,
                                        out, b3, batch, cnt, flag64, N, G);

    k_pool_div<<<(G * DD + 255) / 256, 256>>>(out, cnt, G);
}